// round 2
// baseline (speedup 1.0000x reference)
#include <cuda_runtime.h>
#include <cstdint>

#define BB 512
#define RR 264
#define KK 32
#define SS 9
#define RSTRIDE 36            // padded row stride in floats (144 B, 16B-aligned)
#define NSPLIT 4
#define ROWS_PER (RR / NSPLIT) // 66
#define NTHREADS 160
#define NACT 132               // active compute threads (2 columns each)

__device__ __constant__ int   c_ends[SS]  = {28, 58, 92, 121, 150, 180, 210, 240, 264};
__device__ __constant__ float c_sizes[SS] = {28.f, 30.f, 34.f, 29.f, 29.f, 30.f, 30.f, 30.f, 24.f};

__device__ __forceinline__ unsigned long long fma2(unsigned long long a,
                                                   unsigned long long b,
                                                   unsigned long long c) {
    unsigned long long d;
    asm("fma.rn.f32x2 %0, %1, %2, %3;" : "=l"(d) : "l"(a), "l"(b), "l"(c));
    return d;
}
__device__ __forceinline__ unsigned long long add2(unsigned long long a,
                                                   unsigned long long b) {
    unsigned long long d;
    asm("add.rn.f32x2 %0, %1, %2;" : "=l"(d) : "l"(a), "l"(b));
    return d;
}
__device__ __forceinline__ float sum2(unsigned long long a) {
    return __uint_as_float((unsigned)(a & 0xffffffffull)) +
           __uint_as_float((unsigned)(a >> 32));
}

extern "C" __global__ void __launch_bounds__(NTHREADS, 3)
gram_kernel(const float* __restrict__ E, float* __restrict__ out)
{
    float* intra = out;
    float* inter = out + (size_t)BB * RR * RR;
    float* adj   = inter + (size_t)BB * SS * SS;

    extern __shared__ float sE[];          // [RR][RSTRIDE]
    __shared__ int   sSeg[RR];
    __shared__ float sSum[SS * KK];

    const int b     = blockIdx.y;
    const int split = blockIdx.x;
    const int tid   = threadIdx.x;
    const float* Eb = E + (size_t)b * (RR * KK);

    // ---- cooperative load of E[b] into padded smem (float4 coalesced) ----
    for (int i = tid; i < (RR * KK) / 4; i += NTHREADS) {
        float4 v = reinterpret_cast<const float4*>(Eb)[i];
        int row = i >> 3, kq = i & 7;
        *reinterpret_cast<float4*>(&sE[row * RSTRIDE + kq * 4]) = v;
    }
    // ---- segment id per ROI ----
    for (int i = tid; i < RR; i += NTHREADS) {
        int s = 0;
        #pragma unroll
        for (int j = 0; j < SS; j++) s += (i >= c_ends[j]) ? 1 : 0;
        sSeg[i] = s;
    }
    __syncthreads();

    const bool active = (tid < NACT);
    const int  c0     = active ? 2 * tid : 0;   // two adjacent columns c0, c0+1

    // two column vectors in registers, each 16 x f32x2 (loaded via LDS.128)
    unsigned long long bv0[16], bv1[16];
    #pragma unroll
    for (int q = 0; q < 8; q++) {
        ulonglong2 t0 = *reinterpret_cast<const ulonglong2*>(&sE[c0 * RSTRIDE + 4 * q]);
        ulonglong2 t1 = *reinterpret_cast<const ulonglong2*>(&sE[(c0 + 1) * RSTRIDE + 4 * q]);
        bv0[2 * q] = t0.x; bv0[2 * q + 1] = t0.y;
        bv1[2 * q] = t1.x; bv1[2 * q + 1] = t1.y;
    }
    const int segc0 = sSeg[c0];
    const int segc1 = sSeg[c0 + 1];

    const int r0 = split * ROWS_PER;
    float* adjp   = adj   + (((size_t)b * RR + r0) * RR) + c0;
    float* intrap = intra + (((size_t)b * RR + r0) * RR) + c0;

    #pragma unroll 2
    for (int r = r0; r < r0 + ROWS_PER; r++) {
        const float* arow = &sE[r * RSTRIDE];
        unsigned long long a0 = 0, a1 = 0, b0 = 0, b1 = 0;
        #pragma unroll
        for (int q = 0; q < 8; q++) {
            ulonglong2 ap = *reinterpret_cast<const ulonglong2*>(&arow[4 * q]); // LDS.128 broadcast
            a0 = fma2(ap.x, bv0[2 * q],     a0);
            a1 = fma2(ap.y, bv0[2 * q + 1], a1);
            b0 = fma2(ap.x, bv1[2 * q],     b0);
            b1 = fma2(ap.y, bv1[2 * q + 1], b1);
        }
        float v0 = sum2(add2(a0, a1));
        float v1 = sum2(add2(b0, b1));
        if (active) {
            int segr = sSeg[r];                 // broadcast LDS
            float2 av; av.x = v0; av.y = v1;
            *reinterpret_cast<float2*>(adjp) = av;
            float2 iv;
            iv.x = (segr == segc0) ? v0 : 0.0f;
            iv.y = (segr == segc1) ? v1 : 0.0f;
            *reinterpret_cast<float2*>(intrap) = iv;
        }
        adjp   += RR;
        intrap += RR;
    }

    // ---- inter-network block means, only split-0 CTAs (one per batch) ----
    // inter[b,s,t] = (sum_{r in s} e_r) . (sum_{p in t} e_p) / (n_s * n_t)
    if (split == 0) {
        for (int i = tid; i < SS * KK; i += NTHREADS) {
            int s  = i >> 5;              // i / 32
            int d  = i & 31;              // i % 32
            int st = (s == 0) ? 0 : c_ends[s - 1];
            int en = c_ends[s];
            float a = 0.0f;
            for (int rr2 = st; rr2 < en; rr2++) a += sE[rr2 * RSTRIDE + d];
            sSum[i] = a;
        }
        __syncthreads();
        if (tid < SS * SS) {
            int s = tid / SS, t = tid % SS;
            float a = 0.0f;
            #pragma unroll
            for (int d = 0; d < KK; d++)
                a += sSum[s * KK + d] * sSum[t * KK + d];
            inter[(size_t)b * SS * SS + tid] = a / (c_sizes[s] * c_sizes[t]);
        }
    }
}

extern "C" void kernel_launch(void* const* d_in, const int* in_sizes, int n_in,
                              void* d_out, int out_size)
{
    (void)in_sizes; (void)n_in; (void)out_size;
    const float* E = (const float*)d_in[0];
    float* out = (float*)d_out;

    dim3 grid(NSPLIT, BB);
    size_t smem = (size_t)RR * RSTRIDE * sizeof(float);
    gram_kernel<<<grid, NTHREADS, smem>>>(E, out);
}